// round 1
// baseline (speedup 1.0000x reference)
#include <cuda_runtime.h>
#include <math.h>

#define NB 16
#define NC 33
#define HIN 256
#define WIN 256
#define HF 128
#define WF 128
#define NFLOW 10
#define NPIX (HF * WF)                 // 16384
#define TPB 256
#define TILES 8
#define PIX_PER_BLOCK (NPIX / TILES)   // 2048
#define WARP_BLOCKS (NB * NFLOW * TILES) // 1280
#define SMOOTH_ELEMS (NB * NFLOW * HF * WF) // 2,621,440
#define SMOOTH_BLOCKS 2560             // 2560 * 1024 = SMOOTH_ELEMS
#define NCH (NB * NFLOW * 3)           // 480
#define RES_TOTAL (NB * NC * HF * WF)  // 8,650,752

// Scratch (device globals: allocation-free)
__device__ float g_resized[RES_TOTAL];             // ~34.6 MB
__device__ float g_warp_part[WARP_BLOCKS * 16];    // per-block: 3ch x 5 moments + pixel charb
__device__ float g_smooth_part[SMOOTH_BLOCKS];

// ---------------------------------------------------------------------------
// Kernel 1: align-corners bilinear resize 256x256 -> 128x128, all 33 channels
// Matches reference: fy = y * f32(255/127); y0 = clip(floor(fy), 0, 254);
// rows-first (vertical) interpolation then horizontal.
// ---------------------------------------------------------------------------
__global__ __launch_bounds__(TPB) void resize_kernel(const float* __restrict__ img) {
    int idx = blockIdx.x * TPB + threadIdx.x;
    int x  = idx & (WF - 1);
    int y  = (idx >> 7) & (HF - 1);
    int bc = idx >> 14;

    const float s = (float)(255.0 / 127.0);
    float fy = (float)y * s;
    float fx = (float)x * s;
    int y0 = min(max((int)floorf(fy), 0), HIN - 2);
    int x0 = min(max((int)floorf(fx), 0), WIN - 2);
    float wy = fy - (float)y0;
    float wx = fx - (float)x0;

    const float* p = img + (size_t)bc * (HIN * WIN);
    float v00 = __ldg(p + y0 * WIN + x0);
    float v01 = __ldg(p + y0 * WIN + x0 + 1);
    float v10 = __ldg(p + (y0 + 1) * WIN + x0);
    float v11 = __ldg(p + (y0 + 1) * WIN + x0 + 1);

    float colL = v00 * (1.0f - wy) + v10 * wy;   // rows[..., x0]
    float colR = v01 * (1.0f - wy) + v11 * wy;   // rows[..., x0+1]
    g_resized[idx] = colL * (1.0f - wx) + colR * wx;
}

__device__ __forceinline__ float charb(float d) {
    // (d^2 + EPS^2)^0.4, EPS = 1e-3
    return __powf(d * d + 1.0e-6f, 0.4f);
}

// ---------------------------------------------------------------------------
// Kernel 2: bilinear warp + SSIM moments + pixel charbonnier.
// Block = (b, f, tile). Each block reduces 16 accumulators deterministically.
// ---------------------------------------------------------------------------
__global__ __launch_bounds__(TPB) void warp_kernel(const float* __restrict__ flows) {
    int bidx = blockIdx.x;
    int tile = bidx & (TILES - 1);
    int bf   = bidx >> 3;            // TILES == 8
    int b = bf / NFLOW;
    int f = bf % NFLOW;
    int tid = threadIdx.x;

    const float* fxp = flows + (size_t)(b * 20 + 2 * f) * NPIX;
    const float* fyp = fxp + NPIX;
    const float* srcbase = g_resized + (size_t)(b * NC + 3 + f * 3) * NPIX;
    const float* refbase = g_resized + (size_t)(b * NC + f * 3) * NPIX;

    float acc[16];
#pragma unroll
    for (int i = 0; i < 16; i++) acc[i] = 0.0f;

    int p0 = tile * PIX_PER_BLOCK;
#pragma unroll
    for (int k = 0; k < PIX_PER_BLOCK; k += TPB) {
        int p = p0 + k + tid;
        int x = p & (WF - 1);
        int y = p >> 7;

        float gx = (float)x + __ldg(fxp + p);
        float gy = (float)y + __ldg(fyp + p);
        float x0f = floorf(gx);
        float y0f = floorf(gy);
        float wx = gx - x0f;          // unclipped fractional weights (matches ref)
        float wy = gy - y0f;
        int ix0 = min(max((int)x0f, 0), WF - 1);
        int iy0 = min(max((int)y0f, 0), HF - 1);
        int ix1 = min(ix0 + 1, WF - 1);
        int iy1 = min(iy0 + 1, HF - 1);

        int o00 = iy0 * WF + ix0;
        int o01 = iy0 * WF + ix1;
        int o10 = iy1 * WF + ix0;
        int o11 = iy1 * WF + ix1;

#pragma unroll
        for (int c = 0; c < 3; c++) {
            const float* sp = srcbase + c * NPIX;
            float v00 = __ldg(sp + o00);
            float v01 = __ldg(sp + o01);
            float v10 = __ldg(sp + o10);
            float v11 = __ldg(sp + o11);
            float top = v00 * (1.0f - wx) + v01 * wx;
            float bot = v10 * (1.0f - wx) + v11 * wx;
            float w   = top * (1.0f - wy) + bot * wy;
            float r   = __ldg(refbase + c * NPIX + p);

            acc[c * 5 + 0] += r;
            acc[c * 5 + 1] += w;
            acc[c * 5 + 2] += r * r;
            acc[c * 5 + 3] += w * w;
            acc[c * 5 + 4] += r * w;
            float d = r - w;
            acc[15] += charb(d);
        }
    }

    // Deterministic block reduction: warp shuffles, then 8-warp combine.
    __shared__ float sm[8 * 16];
    int lane = tid & 31;
    int wrp  = tid >> 5;
#pragma unroll
    for (int i = 0; i < 16; i++) {
        float v = acc[i];
#pragma unroll
        for (int o = 16; o > 0; o >>= 1) v += __shfl_down_sync(0xffffffffu, v, o);
        if (lane == 0) sm[wrp * 16 + i] = v;
    }
    __syncthreads();
    if (tid < 16) {
        float s = 0.0f;
#pragma unroll
        for (int w = 0; w < 8; w++) s += sm[w * 16 + tid];
        g_warp_part[bidx * 16 + tid] = s;
    }
}

// ---------------------------------------------------------------------------
// Kernel 3: smoothness. Gradients of flow_x/flow_y along flow-index axis
// (channel stride 2) and along H. torch.gradient style (one-sided edges).
// ---------------------------------------------------------------------------
__global__ __launch_bounds__(TPB) void smooth_kernel(const float* __restrict__ flows) {
    int base = blockIdx.x * (TPB * 4);
    float acc = 0.0f;
#pragma unroll
    for (int k = 0; k < 4; k++) {
        int e = base + k * TPB + threadIdx.x;
        int x  = e & (WF - 1);
        int y  = (e >> 7) & (HF - 1);
        int bi = e >> 14;
        int i  = bi % NFLOW;
        int b  = bi / NFLOW;
        const float* fb = flows + (size_t)b * 20 * NPIX;
        int px = y * WF + x;

#pragma unroll
        for (int comp = 0; comp < 2; comp++) {
            const float* ch = fb + (2 * i + comp) * NPIX;
            // gradient along flow-index axis (channel stride 2)
            float gi;
            if (i == 0)
                gi = __ldg(fb + (2 + comp) * NPIX + px) - __ldg(ch + px);
            else if (i == NFLOW - 1)
                gi = __ldg(ch + px) - __ldg(fb + (2 * (NFLOW - 2) + comp) * NPIX + px);
            else
                gi = 0.5f * (__ldg(fb + (2 * (i + 1) + comp) * NPIX + px) -
                             __ldg(fb + (2 * (i - 1) + comp) * NPIX + px));
            // gradient along H
            float gh;
            if (y == 0)
                gh = __ldg(ch + WF + x) - __ldg(ch + px);
            else if (y == HF - 1)
                gh = __ldg(ch + px) - __ldg(ch + (HF - 2) * WF + x);
            else
                gh = 0.5f * (__ldg(ch + (y + 1) * WF + x) - __ldg(ch + (y - 1) * WF + x));

            acc += charb(gi) + charb(gh);
        }
    }

    __shared__ float sm[8];
    int lane = threadIdx.x & 31;
    int wrp  = threadIdx.x >> 5;
#pragma unroll
    for (int o = 16; o > 0; o >>= 1) acc += __shfl_down_sync(0xffffffffu, acc, o);
    if (lane == 0) sm[wrp] = acc;
    __syncthreads();
    if (threadIdx.x == 0) {
        float s = 0.0f;
#pragma unroll
        for (int w = 0; w < 8; w++) s += sm[w];
        g_smooth_part[blockIdx.x] = s;
    }
}

// ---------------------------------------------------------------------------
// Kernel 4: finalize. Double-precision deterministic reduction + SSIM + combine.
// ---------------------------------------------------------------------------
__global__ __launch_bounds__(TPB) void finalize_kernel(float* __restrict__ out) {
    int tid = threadIdx.x;
    double ssim_s = 0.0, pix_s = 0.0, sm_s = 0.0;

    for (int ch = tid; ch < NCH; ch += TPB) {
        int bf = ch / 3, c = ch % 3;
        double S1 = 0, S2 = 0, S11 = 0, S22 = 0, S12 = 0;
        for (int t = 0; t < TILES; t++) {
            const float* p = g_warp_part + (size_t)(bf * TILES + t) * 16 + c * 5;
            S1 += p[0]; S2 += p[1]; S11 += p[2]; S22 += p[3]; S12 += p[4];
        }
        const double N = (double)NPIX;
        double mu1 = S1 / N, mu2 = S2 / N;
        double var1 = (S11 - S1 * S1 / N) / (N - 1.0);
        double var2 = (S22 - S2 * S2 / N) / (N - 1.0);
        double s12  = (S12 - S1 * S2 / N) / N;
        double num = (2.0 * mu1 * mu2 + 1.0e-4) * (2.0 * s12 + 1.0e-3);
        double den = (mu1 * mu1 + mu2 * mu2 + 1.0e-4) * (var1 + var2 + 1.0e-3);
        ssim_s += num / den;
    }
    for (int i = tid; i < WARP_BLOCKS; i += TPB) pix_s += (double)g_warp_part[i * 16 + 15];
    for (int i = tid; i < SMOOTH_BLOCKS; i += TPB) sm_s += (double)g_smooth_part[i];

    __shared__ double sd[TPB];
    sd[tid] = ssim_s; __syncthreads();
    for (int o = TPB / 2; o > 0; o >>= 1) { if (tid < o) sd[tid] += sd[tid + o]; __syncthreads(); }
    double ssim_tot = sd[0]; __syncthreads();

    sd[tid] = pix_s; __syncthreads();
    for (int o = TPB / 2; o > 0; o >>= 1) { if (tid < o) sd[tid] += sd[tid + o]; __syncthreads(); }
    double pix_tot = sd[0]; __syncthreads();

    sd[tid] = sm_s; __syncthreads();
    for (int o = TPB / 2; o > 0; o >>= 1) { if (tid < o) sd[tid] += sd[tid + o]; __syncthreads(); }

    if (tid == 0) {
        double smooth_tot = sd[0];
        double res = pix_tot / (double)(NB * NFLOW * 3 * NPIX)      // pixel loss (w=1.0)
                   + 0.01 * smooth_tot / (double)SMOOTH_ELEMS       // smooth (w=0.01)
                   + ssim_tot / (double)NCH;                        // ssim (w=1.0)
        out[0] = (float)res;
    }
}

extern "C" void kernel_launch(void* const* d_in, const int* in_sizes, int n_in,
                              void* d_out, int out_size) {
    const float* images = (const float*)d_in[0];  // (16,33,256,256) f32
    const float* flows  = (const float*)d_in[1];  // (16,20,128,128) f32
    (void)in_sizes; (void)n_in; (void)out_size;

    resize_kernel<<<RES_TOTAL / TPB, TPB>>>(images);
    warp_kernel<<<WARP_BLOCKS, TPB>>>(flows);
    smooth_kernel<<<SMOOTH_BLOCKS, TPB>>>(flows);
    finalize_kernel<<<1, TPB>>>((float*)d_out);
}

// round 2
// speedup vs baseline: 1.0553x; 1.0553x over previous
#include <cuda_runtime.h>
#include <math.h>

#define NB 16
#define NC 33
#define HIN 256
#define WIN 256
#define HF 128
#define WF 128
#define NFLOW 10
#define NPIX (HF * WF)                 // 16384
#define TPB 256
#define TILES 8
#define PIX_PER_BLOCK (NPIX / TILES)   // 2048
#define WARP_BLOCKS (NB * NFLOW * TILES) // 1280
#define SMOOTH_ELEMS (NB * NFLOW * HF * WF) // 2,621,440
#define SMOOTH_BLOCKS 2560             // 2560 * 1024 = SMOOTH_ELEMS
#define NCH (NB * NFLOW * 3)           // 480
#define RES_TOTAL (NB * NC * HF * WF)  // 8,650,752
#define FIN_TPB 1024

// Scratch (device globals: allocation-free)
__device__ float g_resized[RES_TOTAL];             // ~34.6 MB
__device__ float g_warp_part[WARP_BLOCKS * 16];    // per-block: 3ch x 5 moments + pixel charb
__device__ float g_smooth_part[SMOOTH_BLOCKS];

// ---------------------------------------------------------------------------
// Kernel 1: align-corners bilinear resize 256x256 -> 128x128, all 33 channels
// ---------------------------------------------------------------------------
__global__ __launch_bounds__(TPB) void resize_kernel(const float* __restrict__ img) {
    int idx = blockIdx.x * TPB + threadIdx.x;
    int x  = idx & (WF - 1);
    int y  = (idx >> 7) & (HF - 1);
    int bc = idx >> 14;

    const float s = (float)(255.0 / 127.0);
    float fy = (float)y * s;
    float fx = (float)x * s;
    int y0 = min(max((int)floorf(fy), 0), HIN - 2);
    int x0 = min(max((int)floorf(fx), 0), WIN - 2);
    float wy = fy - (float)y0;
    float wx = fx - (float)x0;

    const float* p = img + (size_t)bc * (HIN * WIN);
    float v00 = __ldg(p + y0 * WIN + x0);
    float v01 = __ldg(p + y0 * WIN + x0 + 1);
    float v10 = __ldg(p + (y0 + 1) * WIN + x0);
    float v11 = __ldg(p + (y0 + 1) * WIN + x0 + 1);

    float colL = v00 * (1.0f - wy) + v10 * wy;
    float colR = v01 * (1.0f - wy) + v11 * wy;
    g_resized[idx] = colL * (1.0f - wx) + colR * wx;
}

__device__ __forceinline__ float charb(float d) {
    // (d^2 + EPS^2)^0.4, EPS = 1e-3
    return __powf(d * d + 1.0e-6f, 0.4f);
}

// ---------------------------------------------------------------------------
// Kernel 2: bilinear warp + SSIM moments + pixel charbonnier.
// ---------------------------------------------------------------------------
__global__ __launch_bounds__(TPB) void warp_kernel(const float* __restrict__ flows) {
    int bidx = blockIdx.x;
    int tile = bidx & (TILES - 1);
    int bf   = bidx >> 3;            // TILES == 8
    int b = bf / NFLOW;
    int f = bf % NFLOW;
    int tid = threadIdx.x;

    const float* fxp = flows + (size_t)(b * 20 + 2 * f) * NPIX;
    const float* fyp = fxp + NPIX;
    const float* srcbase = g_resized + (size_t)(b * NC + 3 + f * 3) * NPIX;
    const float* refbase = g_resized + (size_t)(b * NC + f * 3) * NPIX;

    float acc[16];
#pragma unroll
    for (int i = 0; i < 16; i++) acc[i] = 0.0f;

    int p0 = tile * PIX_PER_BLOCK;
#pragma unroll
    for (int k = 0; k < PIX_PER_BLOCK; k += TPB) {
        int p = p0 + k + tid;
        int x = p & (WF - 1);
        int y = p >> 7;

        float gx = (float)x + __ldg(fxp + p);
        float gy = (float)y + __ldg(fyp + p);
        float x0f = floorf(gx);
        float y0f = floorf(gy);
        float wx = gx - x0f;
        float wy = gy - y0f;
        int ix0 = min(max((int)x0f, 0), WF - 1);
        int iy0 = min(max((int)y0f, 0), HF - 1);
        int ix1 = min(ix0 + 1, WF - 1);
        int iy1 = min(iy0 + 1, HF - 1);

        int o00 = iy0 * WF + ix0;
        int o01 = iy0 * WF + ix1;
        int o10 = iy1 * WF + ix0;
        int o11 = iy1 * WF + ix1;

#pragma unroll
        for (int c = 0; c < 3; c++) {
            const float* sp = srcbase + c * NPIX;
            float v00 = __ldg(sp + o00);
            float v01 = __ldg(sp + o01);
            float v10 = __ldg(sp + o10);
            float v11 = __ldg(sp + o11);
            float top = v00 * (1.0f - wx) + v01 * wx;
            float bot = v10 * (1.0f - wx) + v11 * wx;
            float w   = top * (1.0f - wy) + bot * wy;
            float r   = __ldg(refbase + c * NPIX + p);

            acc[c * 5 + 0] += r;
            acc[c * 5 + 1] += w;
            acc[c * 5 + 2] += r * r;
            acc[c * 5 + 3] += w * w;
            acc[c * 5 + 4] += r * w;
            float d = r - w;
            acc[15] += charb(d);
        }
    }

    __shared__ float sm[8 * 16];
    int lane = tid & 31;
    int wrp  = tid >> 5;
#pragma unroll
    for (int i = 0; i < 16; i++) {
        float v = acc[i];
#pragma unroll
        for (int o = 16; o > 0; o >>= 1) v += __shfl_down_sync(0xffffffffu, v, o);
        if (lane == 0) sm[wrp * 16 + i] = v;
    }
    __syncthreads();
    if (tid < 16) {
        float s = 0.0f;
#pragma unroll
        for (int w = 0; w < 8; w++) s += sm[w * 16 + tid];
        g_warp_part[bidx * 16 + tid] = s;
    }
}

// ---------------------------------------------------------------------------
// Kernel 3: smoothness gradients (flow-index axis + H axis), charbonnier.
// ---------------------------------------------------------------------------
__global__ __launch_bounds__(TPB) void smooth_kernel(const float* __restrict__ flows) {
    int base = blockIdx.x * (TPB * 4);
    float acc = 0.0f;
#pragma unroll
    for (int k = 0; k < 4; k++) {
        int e = base + k * TPB + threadIdx.x;
        int x  = e & (WF - 1);
        int y  = (e >> 7) & (HF - 1);
        int bi = e >> 14;
        int i  = bi % NFLOW;
        int b  = bi / NFLOW;
        const float* fb = flows + (size_t)b * 20 * NPIX;
        int px = y * WF + x;

#pragma unroll
        for (int comp = 0; comp < 2; comp++) {
            const float* ch = fb + (2 * i + comp) * NPIX;
            float gi;
            if (i == 0)
                gi = __ldg(fb + (2 + comp) * NPIX + px) - __ldg(ch + px);
            else if (i == NFLOW - 1)
                gi = __ldg(ch + px) - __ldg(fb + (2 * (NFLOW - 2) + comp) * NPIX + px);
            else
                gi = 0.5f * (__ldg(fb + (2 * (i + 1) + comp) * NPIX + px) -
                             __ldg(fb + (2 * (i - 1) + comp) * NPIX + px));
            float gh;
            if (y == 0)
                gh = __ldg(ch + WF + x) - __ldg(ch + px);
            else if (y == HF - 1)
                gh = __ldg(ch + px) - __ldg(ch + (HF - 2) * WF + x);
            else
                gh = 0.5f * (__ldg(ch + (y + 1) * WF + x) - __ldg(ch + (y - 1) * WF + x));

            acc += charb(gi) + charb(gh);
        }
    }

    __shared__ float sm[8];
    int lane = threadIdx.x & 31;
    int wrp  = threadIdx.x >> 5;
#pragma unroll
    for (int o = 16; o > 0; o >>= 1) acc += __shfl_down_sync(0xffffffffu, acc, o);
    if (lane == 0) sm[wrp] = acc;
    __syncthreads();
    if (threadIdx.x == 0) {
        float s = 0.0f;
#pragma unroll
        for (int w = 0; w < 8; w++) s += sm[w];
        g_smooth_part[blockIdx.x] = s;
    }
}

// ---------------------------------------------------------------------------
// Kernel 4 (REWRITTEN): finalize with 1024 threads + high-MLP loads.
// Phase A: 2400 threads-worth of (channel,moment) sums, each over 8 tiles,
//          into shared. Pix/smooth partials read coalesced.
// Phase B: per-channel SSIM in double from shared; three deterministic
//          block reductions.
// ---------------------------------------------------------------------------
__global__ __launch_bounds__(FIN_TPB) void finalize_kernel(float* __restrict__ out) {
    int tid = threadIdx.x;

    __shared__ float smom[NCH * 5];        // 2400 floats: per-(bf,c) x 5 moments
    __shared__ double sd[FIN_TPB / 32];    // warp-level partials

    // Phase A1: (bf, c, m) sums over 8 tiles. t = bfc*5 + m.
    for (int t = tid; t < NCH * 5; t += FIN_TPB) {
        int bfc = t / 5;
        int m   = t % 5;
        int bf  = bfc / 3;
        int c   = bfc % 3;
        const float* p = g_warp_part + (size_t)(bf * TILES) * 16 + c * 5 + m;
        float s = 0.0f;
#pragma unroll
        for (int tl = 0; tl < TILES; tl++) s += p[tl * 16];
        smom[t] = s;
    }

    // Phase A2: pixel-charb partials (stride-1024 over 1280 entries)
    double pix_s = 0.0;
    for (int i = tid; i < WARP_BLOCKS; i += FIN_TPB)
        pix_s += (double)g_warp_part[i * 16 + 15];

    // Phase A3: smooth partials (coalesced, 2560 entries)
    double sm_s = 0.0;
    for (int i = tid; i < SMOOTH_BLOCKS; i += FIN_TPB)
        sm_s += (double)g_smooth_part[i];

    __syncthreads();

    // Phase B: per-channel SSIM from shared moments.
    double ssim_s = 0.0;
    for (int ch = tid; ch < NCH; ch += FIN_TPB) {
        const float* m = smom + ch * 5;
        double S1 = m[0], S2 = m[1], S11 = m[2], S22 = m[3], S12 = m[4];
        const double N = (double)NPIX;
        double mu1 = S1 / N, mu2 = S2 / N;
        double var1 = (S11 - S1 * S1 / N) / (N - 1.0);
        double var2 = (S22 - S2 * S2 / N) / (N - 1.0);
        double s12  = (S12 - S1 * S2 / N) / N;
        double num = (2.0 * mu1 * mu2 + 1.0e-4) * (2.0 * s12 + 1.0e-3);
        double den = (mu1 * mu1 + mu2 * mu2 + 1.0e-4) * (var1 + var2 + 1.0e-3);
        ssim_s += num / den;
    }

    // Deterministic reductions: warp shuffle (doubles) then cross-warp.
    int lane = tid & 31;
    int wrp  = tid >> 5;

    // helper pattern repeated for the three sums
#pragma unroll
    for (int o = 16; o > 0; o >>= 1) ssim_s += __shfl_down_sync(0xffffffffu, ssim_s, o);
    if (lane == 0) sd[wrp] = ssim_s;
    __syncthreads();
    double ssim_tot = 0.0;
    if (tid == 0) {
#pragma unroll
        for (int w = 0; w < FIN_TPB / 32; w++) ssim_tot += sd[w];
    }
    __syncthreads();

#pragma unroll
    for (int o = 16; o > 0; o >>= 1) pix_s += __shfl_down_sync(0xffffffffu, pix_s, o);
    if (lane == 0) sd[wrp] = pix_s;
    __syncthreads();
    double pix_tot = 0.0;
    if (tid == 0) {
#pragma unroll
        for (int w = 0; w < FIN_TPB / 32; w++) pix_tot += sd[w];
    }
    __syncthreads();

#pragma unroll
    for (int o = 16; o > 0; o >>= 1) sm_s += __shfl_down_sync(0xffffffffu, sm_s, o);
    if (lane == 0) sd[wrp] = sm_s;
    __syncthreads();

    if (tid == 0) {
        double smooth_tot = 0.0;
#pragma unroll
        for (int w = 0; w < FIN_TPB / 32; w++) smooth_tot += sd[w];
        double res = pix_tot / (double)(NB * NFLOW * 3 * NPIX)      // pixel loss (w=1.0)
                   + 0.01 * smooth_tot / (double)SMOOTH_ELEMS       // smooth (w=0.01)
                   + ssim_tot / (double)NCH;                        // ssim (w=1.0)
        out[0] = (float)res;
    }
}

extern "C" void kernel_launch(void* const* d_in, const int* in_sizes, int n_in,
                              void* d_out, int out_size) {
    const float* images = (const float*)d_in[0];  // (16,33,256,256) f32
    const float* flows  = (const float*)d_in[1];  // (16,20,128,128) f32
    (void)in_sizes; (void)n_in; (void)out_size;

    resize_kernel<<<RES_TOTAL / TPB, TPB>>>(images);
    warp_kernel<<<WARP_BLOCKS, TPB>>>(flows);
    smooth_kernel<<<SMOOTH_BLOCKS, TPB>>>(flows);
    finalize_kernel<<<1, FIN_TPB>>>((float*)d_out);
}

// round 3
// speedup vs baseline: 1.2786x; 1.2117x over previous
#include <cuda_runtime.h>
#include <math.h>

#define NB 16
#define NC 33
#define HIN 256
#define WIN 256
#define HF 128
#define WF 128
#define NFLOW 10
#define NPIX (HF * WF)                 // 16384
#define TPB 256
#define TILES 8
#define PIX_PER_BLOCK (NPIX / TILES)   // 2048
#define WARP_BLOCKS (NB * NFLOW * TILES) // 1280
#define SMOOTH_ELEMS (NB * NFLOW * HF * WF) // 2,621,440
#define SMOOTH_BLOCKS 2560             // 2560 * 1024 = SMOOTH_ELEMS
#define NCH (NB * NFLOW * 3)           // 480
#define RES_TOTAL (NB * NC * HF * WF)  // 8,650,752
#define FIN_TPB 1024

// Scratch (device globals: allocation-free)
__device__ float g_resized[RES_TOTAL];             // ~34.6 MB
__device__ float g_warp_part[WARP_BLOCKS * 16];    // per-block: 3ch x 5 moments + pixel charb
__device__ float g_smooth_part[SMOOTH_BLOCKS];

// ---------------------------------------------------------------------------
// Kernel 1: align-corners bilinear resize 256x256 -> 128x128, all 33 channels
// ---------------------------------------------------------------------------
__global__ __launch_bounds__(TPB) void resize_kernel(const float* __restrict__ img) {
    int idx = blockIdx.x * TPB + threadIdx.x;
    int x  = idx & (WF - 1);
    int y  = (idx >> 7) & (HF - 1);
    int bc = idx >> 14;

    const float s = (float)(255.0 / 127.0);
    float fy = (float)y * s;
    float fx = (float)x * s;
    int y0 = min(max((int)floorf(fy), 0), HIN - 2);
    int x0 = min(max((int)floorf(fx), 0), WIN - 2);
    float wy = fy - (float)y0;
    float wx = fx - (float)x0;

    const float* p = img + (size_t)bc * (HIN * WIN);
    float v00 = __ldg(p + y0 * WIN + x0);
    float v01 = __ldg(p + y0 * WIN + x0 + 1);
    float v10 = __ldg(p + (y0 + 1) * WIN + x0);
    float v11 = __ldg(p + (y0 + 1) * WIN + x0 + 1);

    float colL = v00 * (1.0f - wy) + v10 * wy;
    float colR = v01 * (1.0f - wy) + v11 * wy;
    g_resized[idx] = colL * (1.0f - wx) + colR * wx;
}

__device__ __forceinline__ float charb(float d) {
    // (d^2 + EPS^2)^0.4, EPS = 1e-3
    return __powf(d * d + 1.0e-6f, 0.4f);
}

// ---------------------------------------------------------------------------
// Kernel 2: bilinear warp + SSIM moments + pixel charbonnier.
// ---------------------------------------------------------------------------
__global__ __launch_bounds__(TPB) void warp_kernel(const float* __restrict__ flows) {
    int bidx = blockIdx.x;
    int tile = bidx & (TILES - 1);
    int bf   = bidx >> 3;            // TILES == 8
    int b = bf / NFLOW;
    int f = bf % NFLOW;
    int tid = threadIdx.x;

    const float* fxp = flows + (size_t)(b * 20 + 2 * f) * NPIX;
    const float* fyp = fxp + NPIX;
    const float* srcbase = g_resized + (size_t)(b * NC + 3 + f * 3) * NPIX;
    const float* refbase = g_resized + (size_t)(b * NC + f * 3) * NPIX;

    float acc[16];
#pragma unroll
    for (int i = 0; i < 16; i++) acc[i] = 0.0f;

    int p0 = tile * PIX_PER_BLOCK;
#pragma unroll
    for (int k = 0; k < PIX_PER_BLOCK; k += TPB) {
        int p = p0 + k + tid;
        int x = p & (WF - 1);
        int y = p >> 7;

        float gx = (float)x + __ldg(fxp + p);
        float gy = (float)y + __ldg(fyp + p);
        float x0f = floorf(gx);
        float y0f = floorf(gy);
        float wx = gx - x0f;
        float wy = gy - y0f;
        int ix0 = min(max((int)x0f, 0), WF - 1);
        int iy0 = min(max((int)y0f, 0), HF - 1);
        int ix1 = min(ix0 + 1, WF - 1);
        int iy1 = min(iy0 + 1, HF - 1);

        int o00 = iy0 * WF + ix0;
        int o01 = iy0 * WF + ix1;
        int o10 = iy1 * WF + ix0;
        int o11 = iy1 * WF + ix1;

#pragma unroll
        for (int c = 0; c < 3; c++) {
            const float* sp = srcbase + c * NPIX;
            float v00 = __ldg(sp + o00);
            float v01 = __ldg(sp + o01);
            float v10 = __ldg(sp + o10);
            float v11 = __ldg(sp + o11);
            float top = v00 * (1.0f - wx) + v01 * wx;
            float bot = v10 * (1.0f - wx) + v11 * wx;
            float w   = top * (1.0f - wy) + bot * wy;
            float r   = __ldg(refbase + c * NPIX + p);

            acc[c * 5 + 0] += r;
            acc[c * 5 + 1] += w;
            acc[c * 5 + 2] += r * r;
            acc[c * 5 + 3] += w * w;
            acc[c * 5 + 4] += r * w;
            float d = r - w;
            acc[15] += charb(d);
        }
    }

    __shared__ float sm[8 * 16];
    int lane = tid & 31;
    int wrp  = tid >> 5;
#pragma unroll
    for (int i = 0; i < 16; i++) {
        float v = acc[i];
#pragma unroll
        for (int o = 16; o > 0; o >>= 1) v += __shfl_down_sync(0xffffffffu, v, o);
        if (lane == 0) sm[wrp * 16 + i] = v;
    }
    __syncthreads();
    if (tid < 16) {
        float s = 0.0f;
#pragma unroll
        for (int w = 0; w < 8; w++) s += sm[w * 16 + tid];
        g_warp_part[bidx * 16 + tid] = s;
    }
}

// ---------------------------------------------------------------------------
// Kernel 3: smoothness gradients (flow-index axis + H axis), charbonnier.
// ---------------------------------------------------------------------------
__global__ __launch_bounds__(TPB) void smooth_kernel(const float* __restrict__ flows) {
    int base = blockIdx.x * (TPB * 4);
    float acc = 0.0f;
#pragma unroll
    for (int k = 0; k < 4; k++) {
        int e = base + k * TPB + threadIdx.x;
        int x  = e & (WF - 1);
        int y  = (e >> 7) & (HF - 1);
        int bi = e >> 14;
        int i  = bi % NFLOW;
        int b  = bi / NFLOW;
        const float* fb = flows + (size_t)b * 20 * NPIX;
        int px = y * WF + x;

#pragma unroll
        for (int comp = 0; comp < 2; comp++) {
            const float* ch = fb + (2 * i + comp) * NPIX;
            float gi;
            if (i == 0)
                gi = __ldg(fb + (2 + comp) * NPIX + px) - __ldg(ch + px);
            else if (i == NFLOW - 1)
                gi = __ldg(ch + px) - __ldg(fb + (2 * (NFLOW - 2) + comp) * NPIX + px);
            else
                gi = 0.5f * (__ldg(fb + (2 * (i + 1) + comp) * NPIX + px) -
                             __ldg(fb + (2 * (i - 1) + comp) * NPIX + px));
            float gh;
            if (y == 0)
                gh = __ldg(ch + WF + x) - __ldg(ch + px);
            else if (y == HF - 1)
                gh = __ldg(ch + px) - __ldg(ch + (HF - 2) * WF + x);
            else
                gh = 0.5f * (__ldg(ch + (y + 1) * WF + x) - __ldg(ch + (y - 1) * WF + x));

            acc += charb(gi) + charb(gh);
        }
    }

    __shared__ float sm[8];
    int lane = threadIdx.x & 31;
    int wrp  = threadIdx.x >> 5;
#pragma unroll
    for (int o = 16; o > 0; o >>= 1) acc += __shfl_down_sync(0xffffffffu, acc, o);
    if (lane == 0) sm[wrp] = acc;
    __syncthreads();
    if (threadIdx.x == 0) {
        float s = 0.0f;
#pragma unroll
        for (int w = 0; w < 8; w++) s += sm[w];
        g_smooth_part[blockIdx.x] = s;
    }
}

// ---------------------------------------------------------------------------
// Kernel 4 (ALL-FLOAT): finalize. No FP64 anywhere — sm_103a's FP64 pipe was
// the Round-2 bottleneck. One fused reduction pass.
// ---------------------------------------------------------------------------
__global__ __launch_bounds__(FIN_TPB) void finalize_kernel(float* __restrict__ out) {
    int tid = threadIdx.x;

    __shared__ float smom[NCH * 5];          // 2400 floats: per-(bf,c) x 5 moments
    __shared__ float sred[3 * (FIN_TPB / 32)];

    // Phase A1: per-(channel,moment) sums over the 8 tile partials.
    for (int t = tid; t < NCH * 5; t += FIN_TPB) {
        int bfc = t / 5;
        int m   = t % 5;
        int bf  = bfc / 3;
        int c   = bfc % 3;
        const float* p = g_warp_part + (size_t)(bf * TILES) * 16 + c * 5 + m;
        float s = 0.0f;
#pragma unroll
        for (int tl = 0; tl < TILES; tl++) s += p[tl * 16];
        smom[t] = s;
    }

    // Phase A2/A3: pixel + smooth partial sums (float).
    float pix_s = 0.0f;
    for (int i = tid; i < WARP_BLOCKS; i += FIN_TPB)
        pix_s += g_warp_part[i * 16 + 15];

    float sm_s = 0.0f;
    for (int i = tid; i < SMOOTH_BLOCKS; i += FIN_TPB)
        sm_s += g_smooth_part[i];

    __syncthreads();

    // Phase B: per-channel SSIM in f32 from shared moments.
    float ssim_s = 0.0f;
    for (int ch = tid; ch < NCH; ch += FIN_TPB) {
        const float* m = smom + ch * 5;
        float S1 = m[0], S2 = m[1], S11 = m[2], S22 = m[3], S12 = m[4];
        const float N    = (float)NPIX;
        const float invN = 1.0f / (float)NPIX;
        const float invNm1 = 1.0f / (float)(NPIX - 1);
        float mu1 = S1 * invN, mu2 = S2 * invN;
        float var1 = (S11 - S1 * S1 * invN) * invNm1;
        float var2 = (S22 - S2 * S2 * invN) * invNm1;
        float s12  = (S12 - S1 * S2 * invN) * invN;
        float num = (2.0f * mu1 * mu2 + 1.0e-4f) * (2.0f * s12 + 1.0e-3f);
        float den = (mu1 * mu1 + mu2 * mu2 + 1.0e-4f) * (var1 + var2 + 1.0e-3f);
        ssim_s += num / den;
    }

    // Single fused reduction pass: three floats per thread.
    int lane = tid & 31;
    int wrp  = tid >> 5;
#pragma unroll
    for (int o = 16; o > 0; o >>= 1) {
        ssim_s += __shfl_down_sync(0xffffffffu, ssim_s, o);
        pix_s  += __shfl_down_sync(0xffffffffu, pix_s,  o);
        sm_s   += __shfl_down_sync(0xffffffffu, sm_s,   o);
    }
    if (lane == 0) {
        sred[wrp * 3 + 0] = ssim_s;
        sred[wrp * 3 + 1] = pix_s;
        sred[wrp * 3 + 2] = sm_s;
    }
    __syncthreads();

    if (wrp == 0) {
        // 32 warps -> one warp reduces the 32 triples.
        float a = sred[lane * 3 + 0];
        float b = sred[lane * 3 + 1];
        float c = sred[lane * 3 + 2];
#pragma unroll
        for (int o = 16; o > 0; o >>= 1) {
            a += __shfl_down_sync(0xffffffffu, a, o);
            b += __shfl_down_sync(0xffffffffu, b, o);
            c += __shfl_down_sync(0xffffffffu, c, o);
        }
        if (lane == 0) {
            float res = b * (1.0f / (float)(NB * NFLOW * 3 * NPIX))   // pixel (w=1.0)
                      + 0.01f * c * (1.0f / (float)SMOOTH_ELEMS)      // smooth (w=0.01)
                      + a * (1.0f / (float)NCH);                      // ssim (w=1.0)
            out[0] = res;
        }
    }
}

extern "C" void kernel_launch(void* const* d_in, const int* in_sizes, int n_in,
                              void* d_out, int out_size) {
    const float* images = (const float*)d_in[0];  // (16,33,256,256) f32
    const float* flows  = (const float*)d_in[1];  // (16,20,128,128) f32
    (void)in_sizes; (void)n_in; (void)out_size;

    resize_kernel<<<RES_TOTAL / TPB, TPB>>>(images);
    warp_kernel<<<WARP_BLOCKS, TPB>>>(flows);
    smooth_kernel<<<SMOOTH_BLOCKS, TPB>>>(flows);
    finalize_kernel<<<1, FIN_TPB>>>((float*)d_out);
}